// round 1
// baseline (speedup 1.0000x reference)
#include <cuda_runtime.h>
#include <cuda_bf16.h>
#include <math.h>

// ---------------------------------------------------------------------------
// CrossCBR propagation, CSR-gather formulation.
// Problem constants (fixed by the dataset).
// ---------------------------------------------------------------------------
#define NU 100000
#define NI 200000
#define NB 50000
#define FD 64           // feature dim
#define E_UI 1000000
#define E_UB 500000
#define E_BI 1000000
#define NLAYERS 2       // num_layers input is the constant 2 for this problem

// ---------------------------------------------------------------------------
// Static device scratch (allocation-free rule: __device__ globals).
// ---------------------------------------------------------------------------
// feature ping-pong + accumulators
__device__ float g_featUa[NU * FD];
__device__ float g_featUb[NU * FD];
__device__ float g_featIa[NI * FD];
__device__ float g_featIb[NI * FD];
__device__ float g_featBa[NB * FD];
__device__ float g_featBb[NB * FD];
__device__ float g_accU1[NU * FD];   // item-level user acc
__device__ float g_accI1[NI * FD];   // item-level item acc
__device__ float g_accU2[NU * FD];   // bundle-level user acc
__device__ float g_accB [NB * FD];   // bundle-level bundle acc
__device__ float g_ILb  [NB * FD];   // item-level bundle rep

// CSR structures
__device__ int g_ptr_ui_u[NU + 1];  __device__ int g_col_ui_u[E_UI];
__device__ int g_ptr_ui_i[NI + 1];  __device__ int g_col_ui_i[E_UI];
__device__ int g_ptr_ub_u[NU + 1];  __device__ int g_col_ub_u[E_UB];
__device__ int g_ptr_ub_b[NB + 1];  __device__ int g_col_ub_b[E_UB];
__device__ int g_ptr_bi_b[NB + 1];  __device__ int g_col_bi_b[E_BI];

__device__ int g_cnt_ui_u[NU]; __device__ int g_cnt_ui_i[NI];
__device__ int g_cnt_ub_u[NU]; __device__ int g_cnt_ub_b[NB];
__device__ int g_cnt_bi_b[NB];

__device__ int g_cur_ui_u[NU]; __device__ int g_cur_ui_i[NI];
__device__ int g_cur_ub_u[NU]; __device__ int g_cur_ub_b[NB];
__device__ int g_cur_bi_b[NB];

__device__ int g_bsum[1024];
__device__ int g_boff[1024];

// ---------------------------------------------------------------------------
// Small utility kernels
// ---------------------------------------------------------------------------
__global__ void k_zero_i32(int* __restrict__ p, int n) {
    int i = blockIdx.x * blockDim.x + threadIdx.x;
    int stride = gridDim.x * blockDim.x;
    for (; i < n; i += stride) p[i] = 0;
}

__global__ void k_copy_f32(const float* __restrict__ src, float* __restrict__ dst, int n4) {
    // n4 = number of float4 elements
    int i = blockIdx.x * blockDim.x + threadIdx.x;
    int stride = gridDim.x * blockDim.x;
    const float4* s = (const float4*)src;
    float4* d = (float4*)dst;
    for (; i < n4; i += stride) d[i] = s[i];
}

// ---------------------------------------------------------------------------
// CSR build: count -> scan -> scatter
// ---------------------------------------------------------------------------
__global__ void k_count_pair(const int* __restrict__ row, const int* __restrict__ col,
                             int E, int* __restrict__ cntR, int* __restrict__ cntC) {
    int i = blockIdx.x * blockDim.x + threadIdx.x;
    int stride = gridDim.x * blockDim.x;
    for (; i < E; i += stride) {
        atomicAdd(&cntR[row[i]], 1);
        atomicAdd(&cntC[col[i]], 1);
    }
}

__global__ void k_count_single(const int* __restrict__ row, int E, int* __restrict__ cntR) {
    int i = blockIdx.x * blockDim.x + threadIdx.x;
    int stride = gridDim.x * blockDim.x;
    for (; i < E; i += stride) atomicAdd(&cntR[row[i]], 1);
}

#define SCAN_T 1024

// Phase 1: per-block reduce of counts -> block sums
__global__ void k_scan1(const int* __restrict__ cnt, int n, int* __restrict__ bsum) {
    __shared__ int s[SCAN_T];
    int tid = threadIdx.x;
    int i = blockIdx.x * SCAN_T + tid;
    s[tid] = (i < n) ? cnt[i] : 0;
    __syncthreads();
    for (int off = SCAN_T / 2; off >= 1; off >>= 1) {
        if (tid < off) s[tid] += s[tid + off];
        __syncthreads();
    }
    if (tid == 0) bsum[blockIdx.x] = s[0];
}

// Phase 2: single-block exclusive scan of block sums (nb <= 1024)
__global__ void k_scan2(const int* __restrict__ bsum, int nb, int* __restrict__ boff) {
    __shared__ int s[1024];
    int tid = threadIdx.x;
    int v = (tid < nb) ? bsum[tid] : 0;
    s[tid] = v;
    __syncthreads();
    for (int off = 1; off < 1024; off <<= 1) {
        int t = (tid >= off) ? s[tid - off] : 0;
        __syncthreads();
        s[tid] += t;
        __syncthreads();
    }
    if (tid < nb) boff[tid] = s[tid] - v;   // exclusive
}

// Phase 3: per-block exclusive scan + offset -> row_ptr AND cursor copy
__global__ void k_scan3(const int* __restrict__ cnt, int n,
                        const int* __restrict__ boff,
                        int* __restrict__ ptr, int* __restrict__ cur, int total) {
    __shared__ int s[SCAN_T];
    int tid = threadIdx.x;
    int i = blockIdx.x * SCAN_T + tid;
    int v = (i < n) ? cnt[i] : 0;
    s[tid] = v;
    __syncthreads();
    for (int off = 1; off < SCAN_T; off <<= 1) {
        int t = (tid >= off) ? s[tid - off] : 0;
        __syncthreads();
        s[tid] += t;
        __syncthreads();
    }
    int excl = boff[blockIdx.x] + s[tid] - v;
    if (i < n) { ptr[i] = excl; cur[i] = excl; }
    if (i == n - 1) ptr[n] = total;
}

__global__ void k_scatter_pair(const int* __restrict__ row, const int* __restrict__ col, int E,
                               int* __restrict__ curR, int* __restrict__ colsR,
                               int* __restrict__ curC, int* __restrict__ colsC) {
    int i = blockIdx.x * blockDim.x + threadIdx.x;
    int stride = gridDim.x * blockDim.x;
    for (; i < E; i += stride) {
        int r = row[i], c = col[i];
        colsR[atomicAdd(&curR[r], 1)] = c;
        colsC[atomicAdd(&curC[c], 1)] = r;
    }
}

__global__ void k_scatter_single(const int* __restrict__ row, const int* __restrict__ col, int E,
                                 int* __restrict__ curR, int* __restrict__ colsR) {
    int i = blockIdx.x * blockDim.x + threadIdx.x;
    int stride = gridDim.x * blockDim.x;
    for (; i < E; i += stride) {
        colsR[atomicAdd(&curR[row[i]], 1)] = col[i];
    }
}

// ---------------------------------------------------------------------------
// SPMM: warp per row, unit edge values.
//   outf[r] = sum_{c in nbrs(r)} src[c]
//   acc[r] += outf[r] / max(||outf[r]||_2, 1e-12)     (fused L2-norm + acc)
// Each lane holds a float2 slice of the 64-float row.
// ---------------------------------------------------------------------------
__global__ void __launch_bounds__(256)
k_spmm_norm(const int* __restrict__ ptr, const int* __restrict__ cols,
            const float* __restrict__ src, float* __restrict__ outf,
            float* __restrict__ acc, int nrows) {
    int warp = (blockIdx.x * blockDim.x + threadIdx.x) >> 5;
    int lane = threadIdx.x & 31;
    if (warp >= nrows) return;
    int beg = ptr[warp], end = ptr[warp + 1];
    const float2* __restrict__ s2 = (const float2*)src;
    float sx = 0.f, sy = 0.f;
    int j = beg;
    for (; j + 4 <= end; j += 4) {
        int c0 = cols[j], c1 = cols[j + 1], c2 = cols[j + 2], c3 = cols[j + 3];
        float2 a = s2[c0 * 32 + lane];
        float2 b = s2[c1 * 32 + lane];
        float2 c = s2[c2 * 32 + lane];
        float2 d = s2[c3 * 32 + lane];
        sx += a.x + b.x + c.x + d.x;
        sy += a.y + b.y + c.y + d.y;
    }
    for (; j < end; j++) {
        float2 a = s2[cols[j] * 32 + lane];
        sx += a.x; sy += a.y;
    }
    ((float2*)outf)[warp * 32 + lane] = make_float2(sx, sy);
    // warp-level L2 norm over the 64 floats
    float sq = sx * sx + sy * sy;
    #pragma unroll
    for (int o = 16; o >= 1; o >>= 1) sq += __shfl_xor_sync(0xffffffffu, sq, o);
    float inv = 1.0f / fmaxf(sqrtf(sq), 1e-12f);
    float2* a2 = (float2*)acc + warp * 32 + lane;
    float2 av = *a2;
    av.x += sx * inv;
    av.y += sy * inv;
    *a2 = av;
}

// SPMM with per-row scale 1/(deg + 1e-8) (BI aggregation). No acc.
__global__ void __launch_bounds__(256)
k_spmm_rowmean(const int* __restrict__ ptr, const int* __restrict__ cols,
               const float* __restrict__ src, float* __restrict__ outf, int nrows) {
    int warp = (blockIdx.x * blockDim.x + threadIdx.x) >> 5;
    int lane = threadIdx.x & 31;
    if (warp >= nrows) return;
    int beg = ptr[warp], end = ptr[warp + 1];
    const float2* __restrict__ s2 = (const float2*)src;
    float sx = 0.f, sy = 0.f;
    int j = beg;
    for (; j + 4 <= end; j += 4) {
        int c0 = cols[j], c1 = cols[j + 1], c2 = cols[j + 2], c3 = cols[j + 3];
        float2 a = s2[c0 * 32 + lane];
        float2 b = s2[c1 * 32 + lane];
        float2 c = s2[c2 * 32 + lane];
        float2 d = s2[c3 * 32 + lane];
        sx += a.x + b.x + c.x + d.x;
        sy += a.y + b.y + c.y + d.y;
    }
    for (; j < end; j++) {
        float2 a = s2[cols[j] * 32 + lane];
        sx += a.x; sy += a.y;
    }
    float inv = 1.0f / ((float)(end - beg) + 1e-8f);
    ((float2*)outf)[warp * 32 + lane] = make_float2(sx * inv, sy * inv);
}

// ---------------------------------------------------------------------------
// Final assembly: out = [concat(accU1, accU2) rows NU ; concat(ILb, accB) rows NB]
// ---------------------------------------------------------------------------
__global__ void k_assemble(const float* __restrict__ accU1, const float* __restrict__ accU2,
                           const float* __restrict__ ILb,  const float* __restrict__ accB,
                           float* __restrict__ out) {
    const int totalU = NU * 128;
    const int total = (NU + NB) * 128;
    int i = blockIdx.x * blockDim.x + threadIdx.x;
    int stride = gridDim.x * blockDim.x;
    for (; i < total; i += stride) {
        float v;
        if (i < totalU) {
            int u = i >> 7, d = i & 127;
            v = (d < 64) ? accU1[u * FD + d] : accU2[u * FD + (d - 64)];
        } else {
            int k = i - totalU;
            int b = k >> 7, d = k & 127;
            v = (d < 64) ? ILb[b * FD + d] : accB[b * FD + (d - 64)];
        }
        out[i] = v;
    }
}

// ---------------------------------------------------------------------------
// Host launch sequence (graph-capturable: kernels only, default stream)
// ---------------------------------------------------------------------------
static inline void* sym(const void* s) {
    void* p = nullptr;
    cudaGetSymbolAddress(&p, s);
    return p;
}

extern "C" void kernel_launch(void* const* d_in, const int* in_sizes, int n_in,
                              void* d_out, int out_size) {
    const float* users   = (const float*)d_in[0];
    const float* items   = (const float*)d_in[1];
    const float* bundles = (const float*)d_in[2];
    const int* ui_row = (const int*)d_in[3];
    const int* ui_col = (const int*)d_in[4];
    const int* ub_row = (const int*)d_in[5];
    const int* ub_col = (const int*)d_in[6];
    const int* bi_row = (const int*)d_in[7];
    const int* bi_col = (const int*)d_in[8];
    // d_in[9] = num_layers (constant 2 for this problem; loop unrolled below)
    float* out = (float*)d_out;

    // scratch pointers
    float* featUa = (float*)sym(g_featUa); float* featUb = (float*)sym(g_featUb);
    float* featIa = (float*)sym(g_featIa); float* featIb = (float*)sym(g_featIb);
    float* featBa = (float*)sym(g_featBa); float* featBb = (float*)sym(g_featBb);
    float* accU1 = (float*)sym(g_accU1); float* accI1 = (float*)sym(g_accI1);
    float* accU2 = (float*)sym(g_accU2); float* accB  = (float*)sym(g_accB);
    float* ILb   = (float*)sym(g_ILb);

    int* ptr_ui_u = (int*)sym(g_ptr_ui_u); int* col_ui_u = (int*)sym(g_col_ui_u);
    int* ptr_ui_i = (int*)sym(g_ptr_ui_i); int* col_ui_i = (int*)sym(g_col_ui_i);
    int* ptr_ub_u = (int*)sym(g_ptr_ub_u); int* col_ub_u = (int*)sym(g_col_ub_u);
    int* ptr_ub_b = (int*)sym(g_ptr_ub_b); int* col_ub_b = (int*)sym(g_col_ub_b);
    int* ptr_bi_b = (int*)sym(g_ptr_bi_b); int* col_bi_b = (int*)sym(g_col_bi_b);
    int* cnt_ui_u = (int*)sym(g_cnt_ui_u); int* cnt_ui_i = (int*)sym(g_cnt_ui_i);
    int* cnt_ub_u = (int*)sym(g_cnt_ub_u); int* cnt_ub_b = (int*)sym(g_cnt_ub_b);
    int* cnt_bi_b = (int*)sym(g_cnt_bi_b);
    int* cur_ui_u = (int*)sym(g_cur_ui_u); int* cur_ui_i = (int*)sym(g_cur_ui_i);
    int* cur_ub_u = (int*)sym(g_cur_ub_u); int* cur_ub_b = (int*)sym(g_cur_ub_b);
    int* cur_bi_b = (int*)sym(g_cur_bi_b);
    int* bsum = (int*)sym(g_bsum); int* boff = (int*)sym(g_boff);

    const int T = 256;
    const int GEDGE = 1024;   // grid for edge-parallel grid-stride kernels

    // ---- zero counts ----
    k_zero_i32<<<(NU + T - 1) / T, T>>>(cnt_ui_u, NU);
    k_zero_i32<<<(NI + T - 1) / T, T>>>(cnt_ui_i, NI);
    k_zero_i32<<<(NU + T - 1) / T, T>>>(cnt_ub_u, NU);
    k_zero_i32<<<(NB + T - 1) / T, T>>>(cnt_ub_b, NB);
    k_zero_i32<<<(NB + T - 1) / T, T>>>(cnt_bi_b, NB);

    // ---- count ----
    k_count_pair<<<GEDGE, T>>>(ui_row, ui_col, E_UI, cnt_ui_u, cnt_ui_i);
    k_count_pair<<<GEDGE, T>>>(ub_row, ub_col, E_UB, cnt_ub_u, cnt_ub_b);
    k_count_single<<<GEDGE, T>>>(bi_row, E_BI, cnt_bi_b);

    // ---- scans (count -> row_ptr + cursor) ----
    {
        struct ScanJob { int* cnt; int n; int* ptr; int* cur; int total; };
        ScanJob jobs[5] = {
            { cnt_ui_u, NU, ptr_ui_u, cur_ui_u, E_UI },
            { cnt_ui_i, NI, ptr_ui_i, cur_ui_i, E_UI },
            { cnt_ub_u, NU, ptr_ub_u, cur_ub_u, E_UB },
            { cnt_ub_b, NB, ptr_ub_b, cur_ub_b, E_UB },
            { cnt_bi_b, NB, ptr_bi_b, cur_bi_b, E_BI },
        };
        for (int jj = 0; jj < 5; jj++) {
            int n = jobs[jj].n;
            int nb = (n + SCAN_T - 1) / SCAN_T;
            k_scan1<<<nb, SCAN_T>>>(jobs[jj].cnt, n, bsum);
            k_scan2<<<1, 1024>>>(bsum, nb, boff);
            k_scan3<<<nb, SCAN_T>>>(jobs[jj].cnt, n, boff, jobs[jj].ptr, jobs[jj].cur, jobs[jj].total);
        }
    }

    // ---- scatter ----
    k_scatter_pair<<<GEDGE, T>>>(ui_row, ui_col, E_UI, cur_ui_u, col_ui_u, cur_ui_i, col_ui_i);
    k_scatter_pair<<<GEDGE, T>>>(ub_row, ub_col, E_UB, cur_ub_u, col_ub_u, cur_ub_b, col_ub_b);
    k_scatter_single<<<GEDGE, T>>>(bi_row, bi_col, E_BI, cur_bi_b, col_bi_b);

    // ---- init accumulators (acc = layer-0 features) ----
    k_copy_f32<<<(NU * FD / 4 + T - 1) / T, T>>>(users,   accU1, NU * FD / 4);
    k_copy_f32<<<(NI * FD / 4 + T - 1) / T, T>>>(items,   accI1, NI * FD / 4);
    k_copy_f32<<<(NU * FD / 4 + T - 1) / T, T>>>(users,   accU2, NU * FD / 4);
    k_copy_f32<<<(NB * FD / 4 + T - 1) / T, T>>>(bundles, accB,  NB * FD / 4);

    // grids: 8 warps (= rows) per 256-thread block
    const int GU = (NU + 7) / 8, GI = (NI + 7) / 8, GB = (NB + 7) / 8;

    // ---- item-level propagation over UI graph (2 layers, unrolled) ----
    k_spmm_norm<<<GU, T>>>(ptr_ui_u, col_ui_u, items,  featUa, accU1, NU);  // layer 1 users
    k_spmm_norm<<<GI, T>>>(ptr_ui_i, col_ui_i, users,  featIa, accI1, NI);  // layer 1 items
    k_spmm_norm<<<GU, T>>>(ptr_ui_u, col_ui_u, featIa, featUb, accU1, NU);  // layer 2 users
    k_spmm_norm<<<GI, T>>>(ptr_ui_i, col_ui_i, featUa, featIb, accI1, NI);  // layer 2 items

    // ---- bundle rep: row-mean over BI graph applied to item acc ----
    k_spmm_rowmean<<<GB, T>>>(ptr_bi_b, col_bi_b, accI1, ILb, NB);

    // ---- bundle-level propagation over UB graph ----
    k_spmm_norm<<<GU, T>>>(ptr_ub_u, col_ub_u, bundles, featUa, accU2, NU); // layer 1 users
    k_spmm_norm<<<GB, T>>>(ptr_ub_b, col_ub_b, users,   featBa, accB,  NB); // layer 1 bundles
    k_spmm_norm<<<GU, T>>>(ptr_ub_u, col_ub_u, featBa,  featUb, accU2, NU); // layer 2 users
    k_spmm_norm<<<GB, T>>>(ptr_ub_b, col_ub_b, featUa,  featBb, accB,  NB); // layer 2 bundles

    // ---- assemble output ----
    {
        int total = (NU + NB) * 128;
        int grid = (total + T - 1) / T;
        if (grid > 65535) grid = 65535;
        k_assemble<<<grid, T>>>(accU1, accU2, ILb, accB, out);
    }
}

// round 2
// speedup vs baseline: 1.5390x; 1.5390x over previous
#include <cuda_runtime.h>
#include <cuda_bf16.h>
#include <math.h>

// ---------------------------------------------------------------------------
// CrossCBR propagation — unified-CSR, fully fused formulation.
// ---------------------------------------------------------------------------
#define NU 100000
#define NI 200000
#define NB 50000
#define FD 64
#define E_UI 1000000
#define E_UB 500000
#define E_BI 1000000

// Concatenated node space for all 5 CSR row-sets:
//   seg0: UI user rows   [B0, B1)   neighbors = item ids
//   seg1: UI item rows   [B1, B2)   neighbors = user ids
//   seg2: UB user rows   [B2, B3)   neighbors = bundle ids
//   seg3: UB bundle rows [B3, B4)   neighbors = user ids
//   seg4: BI bundle rows [B4, NTOT) neighbors = item ids
#define B0 0
#define B1 NU                    // 100000
#define B2 (NU + NI)             // 300000
#define B3 (NU + NI + NU)        // 400000
#define B4 (NU + NI + NU + NB)   // 450000
#define NTOT (B4 + NB)           // 500000
#define NPROP B4                 // rows in the fused propagation kernels
#define E_TOT (2 * E_UI + 2 * E_UB + E_BI)   // 4,000,000

// ---------------------------------------------------------------------------
// Static device scratch
// ---------------------------------------------------------------------------
__device__ int   g_cnt[NTOT];
__device__ int   g_cur[NTOT];
__device__ int   g_ptr[NTOT + 1];
__device__ int   g_col[E_TOT];
__device__ int   g_bsum[512];
__device__ int   g_boff[512];
__device__ float g_feat1[NPROP * FD];   // layer-1 outputs, all 4 segments
__device__ float g_accs [NPROP * FD];   // acc staging: feat0 + norm(layer1)
__device__ float g_accI [NI * FD];      // final item-level item acc (for BI rowmean)

// ---------------------------------------------------------------------------
// CSR build
// ---------------------------------------------------------------------------
__global__ void k_zero(int* __restrict__ p, int n) {
    int i = blockIdx.x * blockDim.x + threadIdx.x;
    if (i < n) p[i] = 0;
}

__global__ void k_count(const int* __restrict__ ui_row, const int* __restrict__ ui_col,
                        const int* __restrict__ ub_row, const int* __restrict__ ub_col,
                        const int* __restrict__ bi_row) {
    const int total = E_UI + E_UB + E_BI;
    int i = blockIdx.x * blockDim.x + threadIdx.x;
    int stride = gridDim.x * blockDim.x;
    for (; i < total; i += stride) {
        if (i < E_UI) {
            atomicAdd(&g_cnt[ui_row[i]], 1);
            atomicAdd(&g_cnt[B1 + ui_col[i]], 1);
        } else if (i < E_UI + E_UB) {
            int e = i - E_UI;
            atomicAdd(&g_cnt[B2 + ub_row[e]], 1);
            atomicAdd(&g_cnt[B3 + ub_col[e]], 1);
        } else {
            int e = i - E_UI - E_UB;
            atomicAdd(&g_cnt[B4 + bi_row[e]], 1);
        }
    }
}

#define SCAN_T 1024
#define SCAN_NB ((NTOT + SCAN_T - 1) / SCAN_T)   // 489

__global__ void k_scan1() {
    __shared__ int s[SCAN_T];
    int tid = threadIdx.x;
    int i = blockIdx.x * SCAN_T + tid;
    s[tid] = (i < NTOT) ? g_cnt[i] : 0;
    __syncthreads();
    for (int off = SCAN_T / 2; off >= 1; off >>= 1) {
        if (tid < off) s[tid] += s[tid + off];
        __syncthreads();
    }
    if (tid == 0) g_bsum[blockIdx.x] = s[0];
}

__global__ void k_scan2() {
    __shared__ int s[512];
    int tid = threadIdx.x;
    int v = (tid < SCAN_NB) ? g_bsum[tid] : 0;
    s[tid] = v;
    __syncthreads();
    for (int off = 1; off < 512; off <<= 1) {
        int t = (tid >= off) ? s[tid - off] : 0;
        __syncthreads();
        s[tid] += t;
        __syncthreads();
    }
    if (tid < SCAN_NB) g_boff[tid] = s[tid] - v;   // exclusive
}

__global__ void k_scan3() {
    __shared__ int s[SCAN_T];
    int tid = threadIdx.x;
    int i = blockIdx.x * SCAN_T + tid;
    int v = (i < NTOT) ? g_cnt[i] : 0;
    s[tid] = v;
    __syncthreads();
    for (int off = 1; off < SCAN_T; off <<= 1) {
        int t = (tid >= off) ? s[tid - off] : 0;
        __syncthreads();
        s[tid] += t;
        __syncthreads();
    }
    int excl = g_boff[blockIdx.x] + s[tid] - v;
    if (i < NTOT) { g_ptr[i] = excl; g_cur[i] = excl; }
    if (i == NTOT - 1) g_ptr[NTOT] = E_TOT;
}

__global__ void k_scatter(const int* __restrict__ ui_row, const int* __restrict__ ui_col,
                          const int* __restrict__ ub_row, const int* __restrict__ ub_col,
                          const int* __restrict__ bi_row, const int* __restrict__ bi_col) {
    const int total = E_UI + E_UB + E_BI;
    int i = blockIdx.x * blockDim.x + threadIdx.x;
    int stride = gridDim.x * blockDim.x;
    for (; i < total; i += stride) {
        if (i < E_UI) {
            int r = ui_row[i], c = ui_col[i];
            g_col[atomicAdd(&g_cur[r], 1)] = c;
            g_col[atomicAdd(&g_cur[B1 + c], 1)] = r;
        } else if (i < E_UI + E_UB) {
            int e = i - E_UI;
            int r = ub_row[e], c = ub_col[e];
            g_col[atomicAdd(&g_cur[B2 + r], 1)] = c;
            g_col[atomicAdd(&g_cur[B3 + c], 1)] = r;
        } else {
            int e = i - E_UI - E_UB;
            g_col[atomicAdd(&g_cur[B4 + bi_row[e]], 1)] = bi_col[e];
        }
    }
}

// ---------------------------------------------------------------------------
// Fused layer-1: for every row in segs 0..3,
//   feat1[r] = sum_{c} src_seg[c]
//   accs[r]  = base_seg[r] + feat1[r] / max(||feat1[r]||, 1e-12)
// warp-per-row, lane holds a float2 slice of the 64-float row.
// ---------------------------------------------------------------------------
__device__ __forceinline__ void gather_row(const float2* __restrict__ src,
                                           const int* __restrict__ cols,
                                           int beg, int end, int lane,
                                           float& sx, float& sy) {
    sx = 0.f; sy = 0.f;
    int j = beg;
    for (; j + 4 <= end; j += 4) {
        int c0 = cols[j], c1 = cols[j + 1], c2 = cols[j + 2], c3 = cols[j + 3];
        float2 a = src[c0 * 32 + lane];
        float2 b = src[c1 * 32 + lane];
        float2 c = src[c2 * 32 + lane];
        float2 d = src[c3 * 32 + lane];
        sx += a.x + b.x + c.x + d.x;
        sy += a.y + b.y + c.y + d.y;
    }
    for (; j < end; j++) {
        float2 a = src[cols[j] * 32 + lane];
        sx += a.x; sy += a.y;
    }
}

__device__ __forceinline__ float warp_inv_norm(float sx, float sy) {
    float sq = sx * sx + sy * sy;
    #pragma unroll
    for (int o = 16; o >= 1; o >>= 1) sq += __shfl_xor_sync(0xffffffffu, sq, o);
    return 1.0f / fmaxf(sqrtf(sq), 1e-12f);
}

__global__ void __launch_bounds__(256)
k_layer1(const float* __restrict__ users, const float* __restrict__ items,
         const float* __restrict__ bundles) {
    int warp = (blockIdx.x * blockDim.x + threadIdx.x) >> 5;
    int lane = threadIdx.x & 31;
    if (warp >= NPROP) return;
    int beg = g_ptr[warp], end = g_ptr[warp + 1];

    const float2* src;
    const float2* base;
    if (warp < B1)      { src = (const float2*)items;   base = (const float2*)users   + warp * 32; }
    else if (warp < B2) { src = (const float2*)users;   base = (const float2*)items   + (warp - B1) * 32; }
    else if (warp < B3) { src = (const float2*)bundles; base = (const float2*)users   + (warp - B2) * 32; }
    else                { src = (const float2*)users;   base = (const float2*)bundles + (warp - B3) * 32; }

    float2 b0 = base[lane];   // issue early, overlaps with gather
    float sx, sy;
    gather_row(src, g_col, beg, end, lane, sx, sy);

    ((float2*)g_feat1)[warp * 32 + lane] = make_float2(sx, sy);
    float inv = warp_inv_norm(sx, sy);
    ((float2*)g_accs)[warp * 32 + lane] = make_float2(b0.x + sx * inv, b0.y + sy * inv);
}

// ---------------------------------------------------------------------------
// Fused layer-2: final = accs[r] + norm(layer2 feat).
// seg0/2/3 write straight into out (stride-128 rows); seg1 -> g_accI.
// ---------------------------------------------------------------------------
__global__ void __launch_bounds__(256)
k_layer2(float* __restrict__ out) {
    int warp = (blockIdx.x * blockDim.x + threadIdx.x) >> 5;
    int lane = threadIdx.x & 31;
    if (warp >= NPROP) return;
    int beg = g_ptr[warp], end = g_ptr[warp + 1];

    const float2* f1 = (const float2*)g_feat1;
    const float2* src;
    if (warp < B1)      src = f1 + B1 * 32;   // gather item layer-1 rows
    else if (warp < B2) src = f1;             // gather UI user layer-1 rows
    else if (warp < B3) src = f1 + B3 * 32;   // gather UB bundle layer-1 rows
    else                src = f1 + B2 * 32;   // gather UB user layer-1 rows

    float2 a0 = ((const float2*)g_accs)[warp * 32 + lane];
    float sx, sy;
    gather_row(src, g_col, beg, end, lane, sx, sy);

    float inv = warp_inv_norm(sx, sy);
    float2 v = make_float2(a0.x + sx * inv, a0.y + sy * inv);

    float2* out2 = (float2*)out;
    if (warp < B1)      out2[warp * 64 + lane] = v;                        // users [0:64)
    else if (warp < B2) ((float2*)g_accI)[(warp - B1) * 32 + lane] = v;    // item acc
    else if (warp < B3) out2[(warp - B2) * 64 + 32 + lane] = v;            // users [64:128)
    else                out2[(NU + warp - B3) * 64 + 32 + lane] = v;       // bundles [64:128)
}

// ---------------------------------------------------------------------------
// BI row-mean: out[bundle, 0:64) = (1/(deg+1e-8)) * sum_{i in bundle} accI[i]
// ---------------------------------------------------------------------------
__global__ void __launch_bounds__(256)
k_rowmean(float* __restrict__ out) {
    int warp = (blockIdx.x * blockDim.x + threadIdx.x) >> 5;
    int lane = threadIdx.x & 31;
    if (warp >= NB) return;
    int r = B4 + warp;
    int beg = g_ptr[r], end = g_ptr[r + 1];

    float sx, sy;
    gather_row((const float2*)g_accI, g_col, beg, end, lane, sx, sy);

    float inv = 1.0f / ((float)(end - beg) + 1e-8f);
    ((float2*)out)[(NU + warp) * 64 + lane] = make_float2(sx * inv, sy * inv);
}

// ---------------------------------------------------------------------------
// Host launch sequence (graph-capturable, 9 launches)
// ---------------------------------------------------------------------------
static inline void* sym(const void* s) {
    void* p = nullptr;
    cudaGetSymbolAddress(&p, s);
    return p;
}

extern "C" void kernel_launch(void* const* d_in, const int* in_sizes, int n_in,
                              void* d_out, int out_size) {
    const float* users   = (const float*)d_in[0];
    const float* items   = (const float*)d_in[1];
    const float* bundles = (const float*)d_in[2];
    const int* ui_row = (const int*)d_in[3];
    const int* ui_col = (const int*)d_in[4];
    const int* ub_row = (const int*)d_in[5];
    const int* ub_col = (const int*)d_in[6];
    const int* bi_row = (const int*)d_in[7];
    const int* bi_col = (const int*)d_in[8];
    // d_in[9] = num_layers (constant 2 for this problem; unrolled)
    float* out = (float*)d_out;

    int* cnt = (int*)sym(g_cnt);

    const int T = 256;
    const int GEDGE = 2048;

    // ---- CSR build (unified) ----
    k_zero<<<(NTOT + T - 1) / T, T>>>(cnt, NTOT);
    k_count<<<GEDGE, T>>>(ui_row, ui_col, ub_row, ub_col, bi_row);
    k_scan1<<<SCAN_NB, SCAN_T>>>();
    k_scan2<<<1, 512>>>();
    k_scan3<<<SCAN_NB, SCAN_T>>>();
    k_scatter<<<GEDGE, T>>>(ui_row, ui_col, ub_row, ub_col, bi_row, bi_col);

    // ---- propagation (8 warps = 8 rows per 256-thread block) ----
    const int GP = (NPROP + 7) / 8;
    k_layer1<<<GP, T>>>(users, items, bundles);
    k_layer2<<<GP, T>>>(out);

    // ---- bundle item-level rep straight into out ----
    k_rowmean<<<(NB + 7) / 8, T>>>(out);
}

// round 5
// speedup vs baseline: 1.8317x; 1.1902x over previous
#include <cuda_runtime.h>
#include <cuda_bf16.h>
#include <math.h>

// ---------------------------------------------------------------------------
// CrossCBR propagation — unified-CSR, fused, float4 pair-of-rows gathers.
// Scratch arrays are declared float4 for guaranteed 16B alignment (LDG.128).
// ---------------------------------------------------------------------------
#define NU 100000
#define NI 200000
#define NB 50000
#define FD 64
#define E_UI 1000000
#define E_UB 500000
#define E_BI 1000000

// Concatenated node space for all 5 CSR row-sets:
//   seg0: UI user rows   [B0, B1)   neighbors = item ids
//   seg1: UI item rows   [B1, B2)   neighbors = user ids
//   seg2: UB user rows   [B2, B3)   neighbors = bundle ids
//   seg3: UB bundle rows [B3, B4)   neighbors = user ids
//   seg4: BI bundle rows [B4, NTOT) neighbors = item ids
#define B0 0
#define B1 NU                    // 100000  (even — pairs never straddle)
#define B2 (NU + NI)             // 300000
#define B3 (NU + NI + NU)        // 400000
#define B4 (NU + NI + NU + NB)   // 450000
#define NTOT (B4 + NB)           // 500000
#define NPROP B4
#define E_TOT (2 * E_UI + 2 * E_UB + E_BI)   // 4,000,000

// ---------------------------------------------------------------------------
// Static device scratch. Feature buffers as float4 rows (16 float4 = 64 floats).
// ---------------------------------------------------------------------------
__device__ int    g_cnt[NTOT];
__device__ int    g_cur[NTOT];
__device__ int    g_ptr[NTOT + 1];
__device__ int    g_col[E_TOT];
__device__ int    g_bsum[512];
__device__ float4 g_feat1[NPROP * 16];   // layer-1 outputs, all 4 segments
__device__ float4 g_accs [NPROP * 16];   // acc staging: feat0 + norm(layer1)
__device__ float4 g_accI [NI * 16];      // item-level item acc (for BI rowmean)

// ---------------------------------------------------------------------------
// CSR build
// ---------------------------------------------------------------------------
__global__ void k_init() {
    int i = blockIdx.x * blockDim.x + threadIdx.x;
    int stride = gridDim.x * blockDim.x;
    for (; i < NTOT; i += stride) g_cnt[i] = 0;
}

__global__ void k_count(const int* __restrict__ ui_row, const int* __restrict__ ui_col,
                        const int* __restrict__ ub_row, const int* __restrict__ ub_col,
                        const int* __restrict__ bi_row) {
    const int total = E_UI + E_UB + E_BI;
    int i = blockIdx.x * blockDim.x + threadIdx.x;
    int stride = gridDim.x * blockDim.x;
    for (; i < total; i += stride) {
        if (i < E_UI) {
            atomicAdd(&g_cnt[ui_row[i]], 1);
            atomicAdd(&g_cnt[B1 + ui_col[i]], 1);
        } else if (i < E_UI + E_UB) {
            int e = i - E_UI;
            atomicAdd(&g_cnt[B2 + ub_row[e]], 1);
            atomicAdd(&g_cnt[B3 + ub_col[e]], 1);
        } else {
            int e = i - E_UI - E_UB;
            atomicAdd(&g_cnt[B4 + bi_row[e]], 1);
        }
    }
}

#define SCAN_T 1024
#define SCAN_NB ((NTOT + SCAN_T - 1) / SCAN_T)   // 489

// Phase 1: per-block total of counts
__global__ void k_scan1() {
    __shared__ int s[SCAN_T];
    int tid = threadIdx.x;
    int i = blockIdx.x * SCAN_T + tid;
    s[tid] = (i < NTOT) ? g_cnt[i] : 0;
    __syncthreads();
    for (int off = SCAN_T / 2; off >= 1; off >>= 1) {
        if (tid < off) s[tid] += s[tid + off];
        __syncthreads();
    }
    if (tid == 0) g_bsum[blockIdx.x] = s[0];
}

// Phase 2 (merged): block computes its own offset from bsum, then scans counts.
__global__ void k_scan2() {
    __shared__ int s[SCAN_T];
    __shared__ int blk_off;
    int tid = threadIdx.x;
    int bid = blockIdx.x;

    // block offset = sum of bsum[0..bid)
    int part = 0;
    for (int k = tid; k < bid; k += SCAN_T) part += g_bsum[k];
    s[tid] = part;
    __syncthreads();
    for (int off = SCAN_T / 2; off >= 1; off >>= 1) {
        if (tid < off) s[tid] += s[tid + off];
        __syncthreads();
    }
    if (tid == 0) blk_off = s[0];
    __syncthreads();
    int base = blk_off;
    __syncthreads();

    // inclusive scan of this block's counts
    int i = bid * SCAN_T + tid;
    int v = (i < NTOT) ? g_cnt[i] : 0;
    s[tid] = v;
    __syncthreads();
    for (int off = 1; off < SCAN_T; off <<= 1) {
        int t = (tid >= off) ? s[tid - off] : 0;
        __syncthreads();
        s[tid] += t;
        __syncthreads();
    }
    int excl = base + s[tid] - v;
    if (i < NTOT) { g_ptr[i] = excl; g_cur[i] = excl; }
    if (i == NTOT - 1) g_ptr[NTOT] = E_TOT;
}

__global__ void k_scatter(const int* __restrict__ ui_row, const int* __restrict__ ui_col,
                          const int* __restrict__ ub_row, const int* __restrict__ ub_col,
                          const int* __restrict__ bi_row, const int* __restrict__ bi_col) {
    const int total = E_UI + E_UB + E_BI;
    int i = blockIdx.x * blockDim.x + threadIdx.x;
    int stride = gridDim.x * blockDim.x;
    for (; i < total; i += stride) {
        if (i < E_UI) {
            int r = ui_row[i], c = ui_col[i];
            g_col[atomicAdd(&g_cur[r], 1)] = c;
            g_col[atomicAdd(&g_cur[B1 + c], 1)] = r;
        } else if (i < E_UI + E_UB) {
            int e = i - E_UI;
            int r = ub_row[e], c = ub_col[e];
            g_col[atomicAdd(&g_cur[B2 + r], 1)] = c;
            g_col[atomicAdd(&g_cur[B3 + c], 1)] = r;
        } else {
            int e = i - E_UI - E_UB;
            g_col[atomicAdd(&g_cur[B4 + bi_row[e]], 1)] = bi_col[e];
        }
    }
}

// ---------------------------------------------------------------------------
// Pair-of-rows gather: warp handles rows (2w, 2w+1); lanes [0,16) -> row0,
// lanes [16,32) -> row1. Each lane holds one float4 (16B) of the 64-float row.
// Loop runs to the pair max degree with predicated loads (no divergence split).
// ---------------------------------------------------------------------------
__device__ __forceinline__ float4 gather_row4(const float4* __restrict__ src,
                                              int beg, int deg, int dmax, int hl) {
    float4 acc = make_float4(0.f, 0.f, 0.f, 0.f);
    const int* __restrict__ cols = g_col;
    for (int jj = 0; jj < dmax; jj += 4) {
        #pragma unroll
        for (int k = 0; k < 4; k++) {
            if (jj + k < deg) {
                int c = cols[beg + jj + k];
                float4 v = src[c * 16 + hl];
                acc.x += v.x; acc.y += v.y; acc.z += v.z; acc.w += v.w;
            }
        }
    }
    return acc;
}

__device__ __forceinline__ float half_inv_norm(const float4& a) {
    float sq = a.x * a.x + a.y * a.y + a.z * a.z + a.w * a.w;
    #pragma unroll
    for (int o = 8; o >= 1; o >>= 1) sq += __shfl_xor_sync(0xffffffffu, sq, o);
    return 1.0f / fmaxf(sqrtf(sq), 1e-12f);
}

// layer1: feat1[r] = gather(src_seg); accs[r] = base_seg[r] + norm(feat1[r])
__global__ void __launch_bounds__(256)
k_layer1(const float* __restrict__ users, const float* __restrict__ items,
         const float* __restrict__ bundles) {
    int warp = (blockIdx.x * blockDim.x + threadIdx.x) >> 5;
    if (warp >= NPROP / 2) return;
    int lane = threadIdx.x & 31;
    int hl = lane & 15;
    int r = 2 * warp + (lane >> 4);

    int beg = g_ptr[r], deg = g_ptr[r + 1] - beg;
    int dmax = max(deg, __shfl_xor_sync(0xffffffffu, deg, 16));

    const float4* src;
    const float4* base;
    if (r < B1)      { src = (const float4*)items;   base = (const float4*)users   + r * 16; }
    else if (r < B2) { src = (const float4*)users;   base = (const float4*)items   + (r - B1) * 16; }
    else if (r < B3) { src = (const float4*)bundles; base = (const float4*)users   + (r - B2) * 16; }
    else             { src = (const float4*)users;   base = (const float4*)bundles + (r - B3) * 16; }

    float4 b0 = base[hl];
    float4 s = gather_row4(src, beg, deg, dmax, hl);

    g_feat1[r * 16 + hl] = s;
    float inv = half_inv_norm(s);
    g_accs[r * 16 + hl] =
        make_float4(b0.x + s.x * inv, b0.y + s.y * inv, b0.z + s.z * inv, b0.w + s.w * inv);
}

// layer2: final = accs[r] + norm(gather(feat1_other_seg)); write to out / accI.
__global__ void __launch_bounds__(256)
k_layer2(float* __restrict__ out) {
    int warp = (blockIdx.x * blockDim.x + threadIdx.x) >> 5;
    if (warp >= NPROP / 2) return;
    int lane = threadIdx.x & 31;
    int hl = lane & 15;
    int r = 2 * warp + (lane >> 4);

    int beg = g_ptr[r], deg = g_ptr[r + 1] - beg;
    int dmax = max(deg, __shfl_xor_sync(0xffffffffu, deg, 16));

    const float4* src;
    if (r < B1)      src = g_feat1 + B1 * 16;   // gather item layer-1 rows
    else if (r < B2) src = g_feat1;             // gather UI user layer-1 rows
    else if (r < B3) src = g_feat1 + B3 * 16;   // gather UB bundle layer-1 rows
    else             src = g_feat1 + B2 * 16;   // gather UB user layer-1 rows

    float4 a0 = g_accs[r * 16 + hl];
    float4 s = gather_row4(src, beg, deg, dmax, hl);

    float inv = half_inv_norm(s);
    float4 v = make_float4(a0.x + s.x * inv, a0.y + s.y * inv,
                           a0.z + s.z * inv, a0.w + s.w * inv);

    float4* out4 = (float4*)out;  // out rows are 128 floats = 32 float4
    if (r < B1)      out4[r * 32 + hl] = v;                     // users [0:64)
    else if (r < B2) g_accI[(r - B1) * 16 + hl] = v;            // item acc
    else if (r < B3) out4[(r - B2) * 32 + 16 + hl] = v;         // users [64:128)
    else             out4[(NU + r - B3) * 32 + 16 + hl] = v;    // bundles [64:128)
}

// rowmean: out[bundle, 0:64) = (1/(deg+1e-8)) * sum accI[i]
__global__ void __launch_bounds__(256)
k_rowmean(float* __restrict__ out) {
    int warp = (blockIdx.x * blockDim.x + threadIdx.x) >> 5;
    if (warp >= NB / 2) return;
    int lane = threadIdx.x & 31;
    int hl = lane & 15;
    int b = 2 * warp + (lane >> 4);
    int r = B4 + b;

    int beg = g_ptr[r], deg = g_ptr[r + 1] - beg;
    int dmax = max(deg, __shfl_xor_sync(0xffffffffu, deg, 16));

    float4 s = gather_row4(g_accI, beg, deg, dmax, hl);

    float inv = 1.0f / ((float)deg + 1e-8f);
    ((float4*)out)[(NU + b) * 32 + hl] =
        make_float4(s.x * inv, s.y * inv, s.z * inv, s.w * inv);
}

// ---------------------------------------------------------------------------
// Host launch sequence (graph-capturable, 8 launches)
// ---------------------------------------------------------------------------
extern "C" void kernel_launch(void* const* d_in, const int* in_sizes, int n_in,
                              void* d_out, int out_size) {
    const float* users   = (const float*)d_in[0];
    const float* items   = (const float*)d_in[1];
    const float* bundles = (const float*)d_in[2];
    const int* ui_row = (const int*)d_in[3];
    const int* ui_col = (const int*)d_in[4];
    const int* ub_row = (const int*)d_in[5];
    const int* ub_col = (const int*)d_in[6];
    const int* bi_row = (const int*)d_in[7];
    const int* bi_col = (const int*)d_in[8];
    // d_in[9] = num_layers (constant 2; unrolled)
    float* out = (float*)d_out;

    const int T = 256;
    const int GEDGE = 4096;

    // ---- CSR build ----
    k_init<<<512, T>>>();
    k_count<<<GEDGE, T>>>(ui_row, ui_col, ub_row, ub_col, bi_row);
    k_scan1<<<SCAN_NB, SCAN_T>>>();
    k_scan2<<<SCAN_NB, SCAN_T>>>();
    k_scatter<<<GEDGE, T>>>(ui_row, ui_col, ub_row, ub_col, bi_row, bi_col);

    // ---- propagation: 8 warps = 16 rows per 256-thread block ----
    const int GP = (NPROP / 2 + 7) / 8;
    k_layer1<<<GP, T>>>(users, items, bundles);
    k_layer2<<<GP, T>>>(out);

    // ---- bundle item-level rep ----
    k_rowmean<<<(NB / 2 + 7) / 8, T>>>(out);
}